// round 5
// baseline (speedup 1.0000x reference)
#include <cuda_runtime.h>
#include <cuda_bf16.h>
#include <cstdint>

// ---------------------------------------------------------------------------
// Problem constants
// ---------------------------------------------------------------------------
#define CC     256
#define NTOK   4096
#define BB     2
#define BN     (BB*NTOK)
#define RED    64
#define NH     4
#define HD     16
#define QKV_O  192
#define OPROJ  320
#define LN_EPS 1e-5f
#define ATT_SCALE 0.25f
#define LOG2E  1.4426950408889634f
#define QSCALE (ATT_SCALE * LOG2E)
#define NSPLIT 2
#define KPS    (NTOK/NSPLIT)   // 2048 keys per split

// ---------------------------------------------------------------------------
// Device scratch
// ---------------------------------------------------------------------------
__device__ float g_wcomb[OPROJ * CC];
__device__ float g_Sq[QKV_O];
__device__ float g_Sb[QKV_O];
__device__ float g_mu[BN];
__device__ float g_rsig[BN];
__device__ float g_q[BB * NH * NTOK * HD];          // pre-scaled by QSCALE
__device__ float g_k[BB * NH * NTOK * HD];          // raw f32
__device__ uint32_t g_vt[BB * NH * HD * (NTOK/2)];  // V^T as bf16x2 key-pairs
__device__ float g_dynpart[2 * BN];
__device__ float g_ao[BN * RED];

// split-KV partials ([n][d] contiguous for coalesced access)
__device__ float g_pm[BB * NH * NSPLIT * NTOK];
__device__ float g_pl[BB * NH * NSPLIT * NTOK];
__device__ float g_po[BB * NH * NSPLIT * NTOK * HD];

// ---------------------------------------------------------------------------
// asm helpers
// ---------------------------------------------------------------------------
__device__ __forceinline__ uint32_t pbf16x2(float lo, float hi) {
    uint32_t r; asm("cvt.rn.bf16x2.f32 %0, %1, %2;" : "=r"(r) : "f"(hi), "f"(lo)); return r;
}
__device__ __forceinline__ float ex2f(float x) {
    float r; asm("ex2.approx.f32 %0, %1;" : "=f"(r) : "f"(x)); return r;
}
__device__ __forceinline__ void cpa16(uint32_t saddr, const void* gptr) {
    asm volatile("cp.async.ca.shared.global [%0], [%1], 16;" :: "r"(saddr), "l"(gptr));
}
__device__ __forceinline__ void cpa_commit() {
    asm volatile("cp.async.commit_group;");
}
template <int N>
__device__ __forceinline__ void cpa_wait() {
    asm volatile("cp.async.wait_group %0;" :: "n"(N));
}

__device__ __forceinline__ void mma_tf32_z(float* d, const uint32_t* a, uint32_t b0, uint32_t b1) {
    asm volatile(
        "mma.sync.aligned.m16n8k8.row.col.f32.tf32.tf32.f32 "
        "{%0,%1,%2,%3}, {%4,%5,%6,%7}, {%8,%9}, {%10,%11,%12,%13};"
        : "=f"(d[0]), "=f"(d[1]), "=f"(d[2]), "=f"(d[3])
        : "r"(a[0]), "r"(a[1]), "r"(a[2]), "r"(a[3]), "r"(b0), "r"(b1),
          "f"(0.f), "f"(0.f), "f"(0.f), "f"(0.f));
}
__device__ __forceinline__ void mma_tf32(float* c, const uint32_t* a, uint32_t b0, uint32_t b1) {
    asm volatile(
        "mma.sync.aligned.m16n8k8.row.col.f32.tf32.tf32.f32 "
        "{%0,%1,%2,%3}, {%4,%5,%6,%7}, {%8,%9}, {%0,%1,%2,%3};"
        : "+f"(c[0]), "+f"(c[1]), "+f"(c[2]), "+f"(c[3])
        : "r"(a[0]), "r"(a[1]), "r"(a[2]), "r"(a[3]), "r"(b0), "r"(b1));
}
__device__ __forceinline__ void mma_bf16(float* c, uint32_t a0, uint32_t a1, uint32_t a2, uint32_t a3,
                                         uint32_t b0, uint32_t b1) {
    asm volatile(
        "mma.sync.aligned.m16n8k16.row.col.f32.bf16.bf16.f32 "
        "{%0,%1,%2,%3}, {%4,%5,%6,%7}, {%8,%9}, {%0,%1,%2,%3};"
        : "+f"(c[0]), "+f"(c[1]), "+f"(c[2]), "+f"(c[3])
        : "r"(a0), "r"(a1), "r"(a2), "r"(a3), "r"(b0), "r"(b1));
}

// ---------------------------------------------------------------------------
// Kernel 0: weight prep
// ---------------------------------------------------------------------------
__global__ __launch_bounds__(256) void prep_kernel(const float* __restrict__ qkv_w,
                                                   const float* __restrict__ conv1_w,
                                                   const float* __restrict__ norm_w,
                                                   const float* __restrict__ norm_b) {
    int o = blockIdx.x;
    int c = threadIdx.x;
    __shared__ float r1[256];
    __shared__ float r2[256];
    float wc;
    if (o < QKV_O) {
        float qw = qkv_w[o * CC + c];
        wc = qw * norm_w[c];
        r1[c] = wc;
        r2[c] = qw * norm_b[c];
    } else {
        wc = conv1_w[(o - QKV_O) * CC + c];
        r1[c] = 0.f;
        r2[c] = 0.f;
    }
    g_wcomb[o * CC + c] = wc;
    __syncthreads();
    for (int s = 128; s > 0; s >>= 1) {
        if (c < s) { r1[c] += r1[c + s]; r2[c] += r2[c + s]; }
        __syncthreads();
    }
    if (c == 0 && o < QKV_O) { g_Sq[o] = r1[0]; g_Sb[o] = r2[0]; }
}

// ---------------------------------------------------------------------------
// Kernel 1: LN stats
// ---------------------------------------------------------------------------
__global__ __launch_bounds__(128) void stats_kernel(const float* __restrict__ x) {
    int tok = blockIdx.x * 128 + threadIdx.x;
    int b = tok >> 12;
    int n = tok & (NTOK - 1);
    const float* xp = x + (size_t)b * CC * NTOK + n;
    float s = 0.f, ss = 0.f;
#pragma unroll 8
    for (int c = 0; c < CC; c++) {
        float v = xp[(size_t)c * NTOK];
        s += v;
        ss += v * v;
    }
    float mu = s * (1.f / CC);
    float var = ss * (1.f / CC) - mu * mu;
    g_mu[tok] = mu;
    g_rsig[tok] = rsqrtf(var + LN_EPS);
}

// ---------------------------------------------------------------------------
// Kernel 2: projection GEMM; epilogue writes Q pre-scaled, K f32,
// V as transposed bf16x2, conv branch partials.
// ---------------------------------------------------------------------------
__global__ __launch_bounds__(256) void proj_kernel(const float* __restrict__ x,
                                                   const float* __restrict__ conv1_b,
                                                   const float* __restrict__ conv2_w) {
    extern __shared__ float sm[];
    float* ws = sm;               // 64 x 256
    float* xs = sm + 64 * 256;    // 64 x 128

    int tid = threadIdx.x;
    int oT = blockIdx.y;
    int tokb = blockIdx.x * 128;
    int b = tokb >> 12;
    int nb = tokb & (NTOK - 1);

    for (int i = tid; i < 64 * 256; i += 256)
        ws[i] = g_wcomb[oT * 64 * 256 + i];

    int tx = tid & 15;
    int ty = tid >> 4;

    float acc[4][8];
#pragma unroll
    for (int i = 0; i < 4; i++)
#pragma unroll
        for (int j = 0; j < 8; j++) acc[i][j] = 0.f;

    for (int kc = 0; kc < 4; kc++) {
        __syncthreads();
        for (int i = tid; i < 64 * 128; i += 256) {
            int kk = i >> 7;
            int t = i & 127;
            xs[i] = x[((size_t)b * CC + kc * 64 + kk) * NTOK + nb + t];
        }
        __syncthreads();
#pragma unroll 2
        for (int kk = 0; kk < 64; kk++) {
            int c = kc * 64 + kk;
            float a0 = ws[(ty * 4 + 0) * 256 + c];
            float a1 = ws[(ty * 4 + 1) * 256 + c];
            float a2 = ws[(ty * 4 + 2) * 256 + c];
            float a3 = ws[(ty * 4 + 3) * 256 + c];
            const float* xr = &xs[kk * 128 + tx * 8];
            float4 b0 = *(const float4*)xr;
            float4 b1 = *(const float4*)(xr + 4);
            acc[0][0] += a0 * b0.x; acc[0][1] += a0 * b0.y; acc[0][2] += a0 * b0.z; acc[0][3] += a0 * b0.w;
            acc[0][4] += a0 * b1.x; acc[0][5] += a0 * b1.y; acc[0][6] += a0 * b1.z; acc[0][7] += a0 * b1.w;
            acc[1][0] += a1 * b0.x; acc[1][1] += a1 * b0.y; acc[1][2] += a1 * b0.z; acc[1][3] += a1 * b0.w;
            acc[1][4] += a1 * b1.x; acc[1][5] += a1 * b1.y; acc[1][6] += a1 * b1.z; acc[1][7] += a1 * b1.w;
            acc[2][0] += a2 * b0.x; acc[2][1] += a2 * b0.y; acc[2][2] += a2 * b0.z; acc[2][3] += a2 * b0.w;
            acc[2][4] += a2 * b1.x; acc[2][5] += a2 * b1.y; acc[2][6] += a2 * b1.z; acc[2][7] += a2 * b1.w;
            acc[3][0] += a3 * b0.x; acc[3][1] += a3 * b0.y; acc[3][2] += a3 * b0.z; acc[3][3] += a3 * b0.w;
            acc[3][4] += a3 * b1.x; acc[3][5] += a3 * b1.y; acc[3][6] += a3 * b1.z; acc[3][7] += a3 * b1.w;
        }
    }

    if (oT < 3) {
        float muv[8], rsv[8];
#pragma unroll
        for (int j = 0; j < 8; j++) {
            int tok = tokb + tx * 8 + j;
            muv[j] = g_mu[tok];
            rsv[j] = g_rsig[tok];
        }
#pragma unroll
        for (int i = 0; i < 4; i++) {
            int o = oT * 64 + ty * 4 + i;
            float sq = g_Sq[o];
            float sb = g_Sb[o];
            int which = o >> 6;       // 0=q 1=k 2=v
            int oo = o & 63;
            int h = oo >> 4;
            int d = oo & 15;
            int bh = b * NH + h;
            float val[8];
#pragma unroll
            for (int j = 0; j < 8; j++)
                val[j] = rsv[j] * (acc[i][j] - muv[j] * sq) + sb;
            if (which == 0) {
#pragma unroll
                for (int j = 0; j < 8; j++)
                    g_q[(((size_t)bh * NTOK) + nb + tx * 8 + j) * HD + d] = val[j] * QSCALE;
            } else if (which == 1) {
#pragma unroll
                for (int j = 0; j < 8; j++)
                    g_k[(((size_t)bh * NTOK) + nb + tx * 8 + j) * HD + d] = val[j];
            } else {
                uint4 pk;
                pk.x = pbf16x2(val[0], val[1]);
                pk.y = pbf16x2(val[2], val[3]);
                pk.z = pbf16x2(val[4], val[5]);
                pk.w = pbf16x2(val[6], val[7]);
                *(uint4*)&g_vt[((size_t)bh * HD + d) * (NTOK / 2) + (nb + tx * 8) / 2] = pk;
            }
        }
    } else {
        float part[8];
#pragma unroll
        for (int j = 0; j < 8; j++) part[j] = 0.f;
#pragma unroll
        for (int i = 0; i < 4; i++) {
            int jc = oT * 64 + ty * 4 + i - QKV_O;
            float cb = conv1_b[jc];
            float cw = conv2_w[jc];
#pragma unroll
            for (int j = 0; j < 8; j++) {
                float d1 = fmaxf(acc[i][j] + cb, 0.f);
                part[j] += cw * d1;
            }
        }
        __syncthreads();
        float* red = xs;
#pragma unroll
        for (int j = 0; j < 8; j++) red[ty * 128 + tx * 8 + j] = part[j];
        __syncthreads();
        if (tid < 128) {
            float s = 0.f;
#pragma unroll
            for (int yy = 0; yy < 16; yy++) s += red[yy * 128 + tid];
            g_dynpart[(oT - 3) * BN + tokb + tid] = s;
        }
    }
}

// ---------------------------------------------------------------------------
// Kernel 3: split-KV flash attention, cp.async double-buffered, no in-loop cvt.
// Grid: (NTOK/128, BB*NH, NSPLIT). Emits per-split (m, l, o16) partials.
// ---------------------------------------------------------------------------
#define KT 64
#define QT 128
#define KSTRIDE 20           // f32 words per K row (padded)
#define VSTRIDE 36           // bf16x2 words per V^T row (padded)
#define NTILE (KPS / KT)     // 32

__global__ __launch_bounds__(256) void attn_kernel(int dummy) {
    __shared__ uint32_t ks[2][KT * KSTRIDE];
    __shared__ uint32_t vs[2][HD * VSTRIDE];

    int tid = threadIdx.x;
    int w = tid >> 5;
    int lane = tid & 31;
    int lq = lane >> 2;
    int lc = lane & 3;
    int bh = blockIdx.y;
    int sp = blockIdx.z;
    int qbase = blockIdx.x * QT;

    const uint32_t* gq = (const uint32_t*)(g_q + (size_t)bh * NTOK * HD);
    const float* kg_base = g_k + (size_t)bh * NTOK * HD + (size_t)sp * KPS * HD;
    const uint32_t* vt_base = g_vt + (size_t)bh * HD * (NTOK / 2) + sp * (KPS / 2);

    // Q fragments: direct loads (once)
    uint32_t aq[2][4];
    {
        int r0 = qbase + w * 16 + lq;
#pragma unroll
        for (int kstep = 0; kstep < 2; kstep++) {
            int d0 = 8 * kstep + lc;
            aq[kstep][0] = gq[(size_t)r0 * HD + d0];
            aq[kstep][1] = gq[(size_t)(r0 + 8) * HD + d0];
            aq[kstep][2] = gq[(size_t)r0 * HD + d0 + 4];
            aq[kstep][3] = gq[(size_t)(r0 + 8) * HD + d0 + 4];
        }
    }

    // staging lambdas (by index math; each thread 1 K-chunk, threads<128 also 1 V-chunk)
    int krow = tid >> 2, kdb = (tid & 3) * 4;
    uint32_t kdst0 = __cvta_generic_to_shared(&ks[0][krow * KSTRIDE + kdb]);
    uint32_t kdst1 = __cvta_generic_to_shared(&ks[1][krow * KSTRIDE + kdb]);
    int vrow = tid >> 3, vc8 = (tid & 7) * 4;
    uint32_t vdst0 = __cvta_generic_to_shared(&vs[0][vrow * VSTRIDE + vc8]);
    uint32_t vdst1 = __cvta_generic_to_shared(&vs[1][vrow * VSTRIDE + vc8]);

#define STAGE(bufsel, kt_)                                                        \
    do {                                                                          \
        int kb_ = (kt_) * KT;                                                     \
        cpa16((bufsel) ? kdst1 : kdst0, kg_base + (size_t)(kb_ + krow) * HD + kdb);\
        if (tid < 128)                                                            \
            cpa16((bufsel) ? vdst1 : vdst0,                                       \
                  vt_base + (size_t)vrow * (NTOK / 2) + kb_ / 2 + vc8);           \
        cpa_commit();                                                             \
    } while (0)

    float o[2][4];
#pragma unroll
    for (int i = 0; i < 2; i++)
#pragma unroll
        for (int j = 0; j < 4; j++) o[i][j] = 0.f;
    float m0 = -1e30f, m1 = -1e30f;
    float l0 = 0.f, l1 = 0.f;

    STAGE(0, 0);

    for (int kt = 0; kt < NTILE; kt++) {
        int buf = kt & 1;
        if (kt + 1 < NTILE) {
            STAGE(buf ^ 1, kt + 1);
            cpa_wait<1>();
        } else {
            cpa_wait<0>();
        }
        __syncthreads();

        const uint32_t* kbuf = ks[buf];
        const uint32_t* vbuf = vs[buf];

        // S = Q K^T
        float c[8][4];
#pragma unroll
        for (int nb = 0; nb < 8; nb++) {
            const uint32_t* kr = &kbuf[(nb * 8 + lq) * KSTRIDE + lc];
            mma_tf32_z(c[nb], aq[0], kr[0], kr[4]);
            mma_tf32(c[nb], aq[1], kr[8], kr[12]);
        }

        // online softmax (log2 domain)
        float rm0 = c[0][0], rm1 = c[0][2];
#pragma unroll
        for (int nb = 0; nb < 8; nb++) {
            rm0 = fmaxf(rm0, fmaxf(c[nb][0], c[nb][1]));
            rm1 = fmaxf(rm1, fmaxf(c[nb][2], c[nb][3]));
        }
        rm0 = fmaxf(rm0, __shfl_xor_sync(0xffffffffu, rm0, 1));
        rm0 = fmaxf(rm0, __shfl_xor_sync(0xffffffffu, rm0, 2));
        rm1 = fmaxf(rm1, __shfl_xor_sync(0xffffffffu, rm1, 1));
        rm1 = fmaxf(rm1, __shfl_xor_sync(0xffffffffu, rm1, 2));

        float mn0 = fmaxf(m0, rm0);
        float mn1 = fmaxf(m1, rm1);
        float cor0 = ex2f(m0 - mn0);
        float cor1 = ex2f(m1 - mn1);
        m0 = mn0; m1 = mn1;

        float s0 = 0.f, s1 = 0.f;
#pragma unroll
        for (int nb = 0; nb < 8; nb++) {
            c[nb][0] = ex2f(c[nb][0] - mn0);
            c[nb][1] = ex2f(c[nb][1] - mn0);
            c[nb][2] = ex2f(c[nb][2] - mn1);
            c[nb][3] = ex2f(c[nb][3] - mn1);
            s0 += c[nb][0] + c[nb][1];
            s1 += c[nb][2] + c[nb][3];
        }
        s0 += __shfl_xor_sync(0xffffffffu, s0, 1);
        s0 += __shfl_xor_sync(0xffffffffu, s0, 2);
        s1 += __shfl_xor_sync(0xffffffffu, s1, 1);
        s1 += __shfl_xor_sync(0xffffffffu, s1, 2);
        l0 = l0 * cor0 + s0;
        l1 = l1 * cor1 + s1;

#pragma unroll
        for (int nd = 0; nd < 2; nd++) {
            o[nd][0] *= cor0; o[nd][1] *= cor0;
            o[nd][2] *= cor1; o[nd][3] *= cor1;
        }

        // O += P V
#pragma unroll
        for (int kk = 0; kk < 4; kk++) {
            uint32_t pa0 = pbf16x2(c[2 * kk][0], c[2 * kk][1]);
            uint32_t pa1 = pbf16x2(c[2 * kk][2], c[2 * kk][3]);
            uint32_t pa2 = pbf16x2(c[2 * kk + 1][0], c[2 * kk + 1][1]);
            uint32_t pa3 = pbf16x2(c[2 * kk + 1][2], c[2 * kk + 1][3]);
#pragma unroll
            for (int nd = 0; nd < 2; nd++) {
                int d = 8 * nd + lq;
                uint32_t b0 = vbuf[d * VSTRIDE + lc + 8 * kk];
                uint32_t b1 = vbuf[d * VSTRIDE + lc + 8 * kk + 4];
                mma_bf16(o[nd], pa0, pa1, pa2, pa3, b0, b1);
            }
        }
        __syncthreads();
    }
#undef STAGE

    // partial epilogue (no normalization here; combine folds dyn/l)
    int n0 = qbase + w * 16 + lq;
    int n1 = n0 + 8;
    size_t pb = ((size_t)bh * NSPLIT + sp) * NTOK;
    if (lc == 0) {
        g_pm[pb + n0] = m0;
        g_pm[pb + n1] = m1;
        g_pl[pb + n0] = l0;
        g_pl[pb + n1] = l1;
    }
    float* po0 = g_po + (pb + n0) * HD;
    float* po1 = g_po + (pb + n1) * HD;
#pragma unroll
    for (int nd = 0; nd < 2; nd++) {
        *(float2*)(po0 + 8 * nd + 2 * lc) = make_float2(o[nd][0], o[nd][1]);
        *(float2*)(po1 + 8 * nd + 2 * lc) = make_float2(o[nd][2], o[nd][3]);
    }
}

// ---------------------------------------------------------------------------
// Kernel 3b: combine splits + dyn scaling -> g_ao
// ---------------------------------------------------------------------------
__global__ __launch_bounds__(256) void combine_kernel(const float* __restrict__ conv2_b) {
    int idx = blockIdx.x * 256 + threadIdx.x;     // bh*NTOK + n
    int bh = idx >> 12;
    int n = idx & (NTOK - 1);

    size_t p0 = ((size_t)bh * NSPLIT + 0) * NTOK + n;
    size_t p1 = ((size_t)bh * NSPLIT + 1) * NTOK + n;
    float m0 = g_pm[p0], m1 = g_pm[p1];
    float m = fmaxf(m0, m1);
    float w0 = ex2f(m0 - m);
    float w1 = ex2f(m1 - m);
    float l = g_pl[p0] * w0 + g_pl[p1] * w1;

    int b = bh >> 2;
    int h = bh & 3;
    int tok = b * NTOK + n;
    float dyn = g_dynpart[tok] + g_dynpart[BN + tok] + conv2_b[0];
    float sc = dyn / l;
    float a0 = w0 * sc, a1 = w1 * sc;

    const float4* o0 = (const float4*)(g_po + p0 * HD);
    const float4* o1 = (const float4*)(g_po + p1 * HD);
    float* dst = g_ao + (size_t)tok * RED + h * HD;
#pragma unroll
    for (int i = 0; i < 4; i++) {
        float4 u = o0[i];
        float4 v = o1[i];
        float4 r = make_float4(u.x * a0 + v.x * a1, u.y * a0 + v.y * a1,
                               u.z * a0 + v.z * a1, u.w * a0 + v.w * a1);
        *(float4*)(dst + 4 * i) = r;
    }
}

// ---------------------------------------------------------------------------
// Kernel 4: out-projection + residual + sigmoid
// ---------------------------------------------------------------------------
__global__ __launch_bounds__(256) void out_kernel(const float* __restrict__ x,
                                                  const float* __restrict__ out_w,
                                                  const float* __restrict__ gamma,
                                                  float* __restrict__ out) {
    __shared__ float wsl[64 * 64];
    __shared__ float aos[64 * 64];
    int tid = threadIdx.x;
    int tokb = blockIdx.x * 64;
    int cT = blockIdx.y;
    int b = tokb >> 12;
    int nb = tokb & (NTOK - 1);

    for (int i = tid; i < 64 * 64; i += 256) {
        int t = i >> 6;
        int r = i & 63;
        aos[r * 64 + t] = g_ao[(size_t)(tokb + t) * RED + r];
        wsl[r * 64 + t] = out_w[(size_t)(cT * 64 + t) * RED + r];
    }
    __syncthreads();

    int tx = tid & 15;
    int ty = tid >> 4;
    float acc[4][4];
#pragma unroll
    for (int i = 0; i < 4; i++)
#pragma unroll
        for (int j = 0; j < 4; j++) acc[i][j] = 0.f;

#pragma unroll 4
    for (int r = 0; r < 64; r++) {
        float a0 = wsl[r * 64 + ty * 4 + 0];
        float a1 = wsl[r * 64 + ty * 4 + 1];
        float a2 = wsl[r * 64 + ty * 4 + 2];
        float a3 = wsl[r * 64 + ty * 4 + 3];
        float4 bv = *(const float4*)&aos[r * 64 + tx * 4];
        acc[0][0] += a0 * bv.x; acc[0][1] += a0 * bv.y; acc[0][2] += a0 * bv.z; acc[0][3] += a0 * bv.w;
        acc[1][0] += a1 * bv.x; acc[1][1] += a1 * bv.y; acc[1][2] += a1 * bv.z; acc[1][3] += a1 * bv.w;
        acc[2][0] += a2 * bv.x; acc[2][1] += a2 * bv.y; acc[2][2] += a2 * bv.z; acc[2][3] += a2 * bv.w;
        acc[3][0] += a3 * bv.x; acc[3][1] += a3 * bv.y; acc[3][2] += a3 * bv.z; acc[3][3] += a3 * bv.w;
    }

    float g = gamma[0];
#pragma unroll
    for (int i = 0; i < 4; i++) {
        int c = cT * 64 + ty * 4 + i;
        size_t base = ((size_t)b * CC + c) * NTOK + nb + tx * 4;
        float4 xv = *(const float4*)(x + base);
        float4 r;
        float z0 = g * acc[i][0] + xv.x;
        float z1 = g * acc[i][1] + xv.y;
        float z2 = g * acc[i][2] + xv.z;
        float z3 = g * acc[i][3] + xv.w;
        r.x = 1.f / (1.f + __expf(-z0));
        r.y = 1.f / (1.f + __expf(-z1));
        r.z = 1.f / (1.f + __expf(-z2));
        r.w = 1.f / (1.f + __expf(-z3));
        *(float4*)(out + base) = r;
    }
}

// ---------------------------------------------------------------------------
// Launch
// ---------------------------------------------------------------------------
extern "C" void kernel_launch(void* const* d_in, const int* in_sizes, int n_in,
                              void* d_out, int out_size) {
    const float* x       = (const float*)d_in[0];
    const float* norm_w  = (const float*)d_in[1];
    const float* norm_b  = (const float*)d_in[2];
    const float* qkv_w   = (const float*)d_in[3];
    const float* out_w   = (const float*)d_in[4];
    const float* conv1_w = (const float*)d_in[5];
    const float* conv1_b = (const float*)d_in[6];
    const float* conv2_w = (const float*)d_in[7];
    const float* conv2_b = (const float*)d_in[8];
    const float* gamma   = (const float*)d_in[9];
    float* out = (float*)d_out;
    (void)in_sizes; (void)n_in; (void)out_size;

    const int proj_smem = (64 * 256 + 64 * 128) * sizeof(float);
    cudaFuncSetAttribute(proj_kernel, cudaFuncAttributeMaxDynamicSharedMemorySize, proj_smem);

    prep_kernel<<<OPROJ, 256>>>(qkv_w, conv1_w, norm_w, norm_b);
    stats_kernel<<<BN / 128, 128>>>(x);
    proj_kernel<<<dim3(BN / 128, 5), 256, proj_smem>>>(x, conv1_b, conv2_w);
    attn_kernel<<<dim3(NTOK / QT, BB * NH, NSPLIT), 256>>>(0);
    combine_kernel<<<BB * NH * NTOK / 256, 256>>>(conv2_b);
    out_kernel<<<dim3(BN / 64, CC / 64), 256>>>(x, out_w, gamma, out);
}